// round 4
// baseline (speedup 1.0000x reference)
#include <cuda_runtime.h>
#include <math.h>

// AttentionST: attention pooling, two-kernel split.
// K1 (streaming, balanced): t[r] = E[r]·w_att, p[r] = E[r]·w_pred for all B*S rows.
// K2 (tiny): per-b softmax over t, weighted sum of p, sigmoid.

constexpr int D = 768;
constexpr int S = 512;
constexpr int MAXROWS = 256 * 512;
constexpr int NTHREADS = 256;
constexpr int NWARPS = NTHREADS / 32;
constexpr int F4_PER_ROW = D / 4;             // 192
constexpr int F4_PER_LANE = F4_PER_ROW / 32;  // 6
constexpr int GRID1 = 296;                    // 2 * 148 SMs, fully resident

__device__ float2 g_tp[MAXROWS];              // 1 MB scratch (t, p) per row

__global__ __launch_bounds__(NTHREADS, 2) void dot_kernel(
    const float* __restrict__ E,
    const float* __restrict__ w_att,
    const float* __restrict__ w_pred,
    int total_rows)
{
    const int warp = threadIdx.x >> 5;
    const int lane = threadIdx.x & 31;

    // Both weight vectors register-resident (48 regs), fixed per lane.
    float4 wa[F4_PER_LANE], wp[F4_PER_LANE];
    #pragma unroll
    for (int j = 0; j < F4_PER_LANE; j++) {
        wa[j] = reinterpret_cast<const float4*>(w_att)[j * 32 + lane];
        wp[j] = reinterpret_cast<const float4*>(w_pred)[j * 32 + lane];
    }

    const float4* E4 = reinterpret_cast<const float4*>(E);
    const int gw = blockIdx.x * NWARPS + warp;      // global warp id
    const int stride = GRID1 * NWARPS * 2;          // rows consumed per grid step

    // Each warp processes 2 adjacent rows per iteration, strided over the
    // whole B*S row space: perfectly balanced, no barriers.
    for (int row = gw * 2; row < total_rows; row += stride) {
        const float4* r0 = E4 + (size_t)row * F4_PER_ROW;
        const float4* r1 = r0 + F4_PER_ROW;

        // 12 independent LDG.128 front-batched for MLP.
        float4 v0[F4_PER_LANE], v1[F4_PER_LANE];
        #pragma unroll
        for (int j = 0; j < F4_PER_LANE; j++) v0[j] = r0[j * 32 + lane];
        #pragma unroll
        for (int j = 0; j < F4_PER_LANE; j++) v1[j] = r1[j * 32 + lane];

        float t0 = 0.f, p0 = 0.f, t1 = 0.f, p1 = 0.f;
        float t0b = 0.f, p0b = 0.f, t1b = 0.f, p1b = 0.f;
        #pragma unroll
        for (int j = 0; j < F4_PER_LANE; j++) {
            t0  = fmaf(v0[j].x, wa[j].x, t0);
            t0b = fmaf(v0[j].y, wa[j].y, t0b);
            t0  = fmaf(v0[j].z, wa[j].z, t0);
            t0b = fmaf(v0[j].w, wa[j].w, t0b);
            p0  = fmaf(v0[j].x, wp[j].x, p0);
            p0b = fmaf(v0[j].y, wp[j].y, p0b);
            p0  = fmaf(v0[j].z, wp[j].z, p0);
            p0b = fmaf(v0[j].w, wp[j].w, p0b);
            t1  = fmaf(v1[j].x, wa[j].x, t1);
            t1b = fmaf(v1[j].y, wa[j].y, t1b);
            t1  = fmaf(v1[j].z, wa[j].z, t1);
            t1b = fmaf(v1[j].w, wa[j].w, t1b);
            p1  = fmaf(v1[j].x, wp[j].x, p1);
            p1b = fmaf(v1[j].y, wp[j].y, p1b);
            p1  = fmaf(v1[j].z, wp[j].z, p1);
            p1b = fmaf(v1[j].w, wp[j].w, p1b);
        }
        t0 += t0b; p0 += p0b; t1 += t1b; p1 += p1b;

        #pragma unroll
        for (int o = 16; o; o >>= 1) {
            t0 += __shfl_xor_sync(0xffffffffu, t0, o);
            p0 += __shfl_xor_sync(0xffffffffu, p0, o);
            t1 += __shfl_xor_sync(0xffffffffu, t1, o);
            p1 += __shfl_xor_sync(0xffffffffu, p1, o);
        }
        if (lane == 0) {
            g_tp[row]     = make_float2(t0, p0);
            g_tp[row + 1] = make_float2(t1, p1);
        }
    }
}

// One CTA per batch row: softmax over S scores + weighted sum. Scratch is
// L2-resident (1 MB); this kernel is a few microseconds.
__global__ __launch_bounds__(NTHREADS) void softmax_kernel(
    const float* __restrict__ b_pred,
    float* __restrict__ out)
{
    __shared__ float red[2 * NWARPS];
    const int b    = blockIdx.x;
    const int tid  = threadIdx.x;
    const int warp = tid >> 5;
    const int lane = tid & 31;

    // Each thread owns 2 of the 512 rows.
    float2 a0 = g_tp[b * S + tid];
    float2 a1 = g_tp[b * S + NTHREADS + tid];

    // Max over scores.
    float m = fmaxf(a0.x, a1.x);
    #pragma unroll
    for (int o = 16; o; o >>= 1) m = fmaxf(m, __shfl_xor_sync(0xffffffffu, m, o));
    if (lane == 0) red[warp] = m;
    __syncthreads();
    if (warp == 0) {
        float mm = (lane < NWARPS) ? red[lane] : -INFINITY;
        #pragma unroll
        for (int o = 16; o; o >>= 1) mm = fmaxf(mm, __shfl_xor_sync(0xffffffffu, mm, o));
        if (lane == 0) red[0] = mm;
    }
    __syncthreads();
    m = red[0];

    float e0 = __expf(a0.x - m), e1 = __expf(a1.x - m);
    float se  = e0 + e1;
    float sep = e0 * a0.y + e1 * a1.y;
    #pragma unroll
    for (int o = 16; o; o >>= 1) {
        se  += __shfl_xor_sync(0xffffffffu, se, o);
        sep += __shfl_xor_sync(0xffffffffu, sep, o);
    }
    __syncthreads();
    if (lane == 0) { red[warp] = se; red[NWARPS + warp] = sep; }
    __syncthreads();
    if (tid == 0) {
        float tse = 0.f, tsep = 0.f;
        #pragma unroll
        for (int w = 0; w < NWARPS; w++) { tse += red[w]; tsep += red[NWARPS + w]; }
        float logit = tsep / tse + b_pred[0];
        out[b] = 1.f / (1.f + __expf(-logit));
    }
}

extern "C" void kernel_launch(void* const* d_in, const int* in_sizes, int n_in,
                              void* d_out, int out_size)
{
    const float* E      = (const float*)d_in[0];
    const float* w_att  = (const float*)d_in[1];
    const float* w_pred = (const float*)d_in[2];
    const float* b_pred = (const float*)d_in[3];
    float* out = (float*)d_out;

    const int B = in_sizes[0] / (S * D);
    const int total_rows = B * S;

    dot_kernel<<<GRID1, NTHREADS>>>(E, w_att, w_pred, total_rows);
    softmax_kernel<<<B, NTHREADS>>>(b_pred, out);
}